// round 13
// baseline (speedup 1.0000x reference)
#include <cuda_runtime.h>
#include <cstdint>

// Problem constants
#define BATCH   8
#define T_SEQ   512
#define DMODEL  1024
#define NH      16
#define DK      64
#define S_REL   1023          // 2T-1
#define BT      (BATCH*T_SEQ) // 4096
#define THREE_D (3*DMODEL)    // 3072

// Scratch (device globals; no allocation allowed)
__device__ float g_qkv[BT * THREE_D];   // [B,T, 3D]  (q | k | v per row)
__device__ float g_p[S_REL * DMODEL];   // [S, D] positional projection
__device__ float g_ctx[BT * DMODEL];    // [B,T,D] attention context

// ===========================================================================
// Shared mma helpers
// ===========================================================================
__device__ __forceinline__ uint32_t f2tf32(float f) {
    uint32_t r;
    asm("cvt.rna.tf32.f32 %0, %1;" : "=r"(r) : "f"(f));
    return r;
}
__device__ __forceinline__ void split_tf32(float v, uint32_t& hi, uint32_t& lo) {
    hi = f2tf32(v);
    lo = f2tf32(v - __uint_as_float(hi));
}
__device__ __forceinline__ void mma_tf32(float* d,
                                         uint32_t a0, uint32_t a1, uint32_t a2, uint32_t a3,
                                         uint32_t b0, uint32_t b1) {
    asm volatile(
        "mma.sync.aligned.m16n8k8.row.col.f32.tf32.tf32.f32 "
        "{%0,%1,%2,%3}, {%4,%5,%6,%7}, {%8,%9}, {%0,%1,%2,%3};"
        : "+f"(d[0]), "+f"(d[1]), "+f"(d[2]), "+f"(d[3])
        : "r"(a0), "r"(a1), "r"(a2), "r"(a3), "r"(b0), "r"(b1));
}
// kperm layout: within a 32-wide k chunk, element k stored at (k%4)*8 + k/4.
#define KPERM(k) ((((k)&3)<<3) | ((k)>>2))

// A fragment (m16, all 4 k-steps of a 32-chunk) from a [rows][36] tile
__device__ __forceinline__ void frag_a36(const uint32_t* t, int row0, int lane,
                                         uint32_t a[2][8]) {
#pragma unroll
    for (int hh = 0; hh < 2; hh++) {
        const uint4* p = (const uint4*)(t + (size_t)(row0 + (lane >> 2) + hh * 8) * 36
                                          + (lane & 3) * 8);
        uint4 x = p[0], y = p[1];
        a[hh][0] = x.x; a[hh][1] = x.y; a[hh][2] = x.z; a[hh][3] = x.w;
        a[hh][4] = y.x; a[hh][5] = y.y; a[hh][6] = y.z; a[hh][7] = y.w;
    }
}
// B fragment (n8, all 4 k-steps of a 32-chunk)
__device__ __forceinline__ void frag_b36(const uint32_t* t, int row0, int lane,
                                         uint32_t bfr[8]) {
    const uint4* p = (const uint4*)(t + (size_t)(row0 + (lane >> 2)) * 36
                                      + (lane & 3) * 8);
    uint4 x = p[0], y = p[1];
    bfr[0] = x.x; bfr[1] = x.y; bfr[2] = x.z; bfr[3] = x.w;
    bfr[4] = y.x; bfr[5] = y.y; bfr[6] = y.z; bfr[7] = y.w;
}
// split-precision k-step: acc += Ahi*Bhi + Ahi*Blo + Alo*Bhi
__device__ __forceinline__ void mma3(float* acc,
                                     const uint32_t ah[2][8], const uint32_t al[2][8],
                                     const uint32_t bh[8], const uint32_t bl[8], int ks) {
    mma_tf32(acc, ah[0][2*ks], ah[1][2*ks], ah[0][2*ks+1], ah[1][2*ks+1],
             bh[2*ks], bh[2*ks+1]);
    mma_tf32(acc, ah[0][2*ks], ah[1][2*ks], ah[0][2*ks+1], ah[1][2*ks+1],
             bl[2*ks], bl[2*ks+1]);
    mma_tf32(acc, al[0][2*ks], al[1][2*ks], al[0][2*ks+1], al[1][2*ks+1],
             bh[2*ks], bh[2*ks+1]);
}

// ===========================================================================
// tf32 mma.sync GEMM (NT): C[M,N] = A[M,K] @ B[N,K]^T + bias[N]
// (round-8 champion, unchanged)
// ===========================================================================
#define PITCH 36
#define TILE_F (128 * PITCH)
#define GEMM_SMEM (2 * 2 * TILE_F * 4)         // 73728 bytes

__global__ __launch_bounds__(256, 1)
void gemm_tf32(const float* __restrict__ A, const float* __restrict__ Bm,
               const float* __restrict__ bias, float* __restrict__ C,
               int M, int N, int K)
{
    extern __shared__ __align__(16) float smem[];

    const int tid  = threadIdx.x;
    const int lane = tid & 31;
    const int w    = tid >> 5;
    const int wm   = w & 3;
    const int wn   = w >> 2;

    const int n0 = blockIdx.x * 128;
    const int m0 = blockIdx.y * 128;

    const int lrow = w * 8 + (lane >> 2);
    const int lq   = lane & 3;

    float acc[2][8][4];
#pragma unroll
    for (int mi = 0; mi < 2; mi++)
#pragma unroll
        for (int ni = 0; ni < 8; ni++)
#pragma unroll
            for (int r = 0; r < 4; r++) acc[mi][ni][r] = 0.f;

    const int nc = K >> 5;
    float4 sa[4], sb[4];

#pragma unroll
    for (int i = 0; i < 4; i++) {
        int row = lrow + (i & 1) * 64;
        int q   = lq + 4 * (i >> 1);
        sa[i] = make_float4(0.f, 0.f, 0.f, 0.f);
        if (m0 + row < M)
            sa[i] = *(const float4*)(A + (size_t)(m0 + row) * K + q * 4);
        sb[i] = *(const float4*)(Bm + (size_t)(n0 + row) * K + q * 4);
    }
    {
        float* As = smem;
        float* Bs = smem + TILE_F;
#pragma unroll
        for (int i = 0; i < 4; i++) {
            int row = lrow + (i & 1) * 64;
            int q   = lq + 4 * (i >> 1);
            float* ar = As + row * PITCH + q;
            float* br = Bs + row * PITCH + q;
            ((uint32_t*)ar)[0]  = f2tf32(sa[i].x);
            ((uint32_t*)ar)[8]  = f2tf32(sa[i].y);
            ((uint32_t*)ar)[16] = f2tf32(sa[i].z);
            ((uint32_t*)ar)[24] = f2tf32(sa[i].w);
            ((uint32_t*)br)[0]  = f2tf32(sb[i].x);
            ((uint32_t*)br)[8]  = f2tf32(sb[i].y);
            ((uint32_t*)br)[16] = f2tf32(sb[i].z);
            ((uint32_t*)br)[24] = f2tf32(sb[i].w);
        }
    }
    __syncthreads();

    for (int c = 0; c < nc; c++) {
        if (c + 1 < nc) {
            const int k0 = (c + 1) << 5;
#pragma unroll
            for (int i = 0; i < 4; i++) {
                int row = lrow + (i & 1) * 64;
                int q   = lq + 4 * (i >> 1);
                sa[i] = make_float4(0.f, 0.f, 0.f, 0.f);
                if (m0 + row < M)
                    sa[i] = *(const float4*)(A + (size_t)(m0 + row) * K + k0 + q * 4);
                sb[i] = *(const float4*)(Bm + (size_t)(n0 + row) * K + k0 + q * 4);
            }
        }

        const float* As = smem + (c & 1) * 2 * TILE_F;
        const float* Bs = As + TILE_F;

        uint32_t ar[2][2][8];
#pragma unroll
        for (int mi = 0; mi < 2; mi++)
            frag_a36((const uint32_t*)As, wm * 32 + mi * 16, lane, ar[mi]);
        uint32_t br[8][8];
#pragma unroll
        for (int ni = 0; ni < 8; ni++)
            frag_b36((const uint32_t*)Bs, wn * 64 + ni * 8, lane, br[ni]);

#pragma unroll
        for (int ks = 0; ks < 4; ks++)
#pragma unroll
            for (int mi = 0; mi < 2; mi++)
#pragma unroll
                for (int ni = 0; ni < 8; ni++)
                    mma_tf32(acc[mi][ni],
                             ar[mi][0][2 * ks], ar[mi][1][2 * ks],
                             ar[mi][0][2 * ks + 1], ar[mi][1][2 * ks + 1],
                             br[ni][2 * ks], br[ni][2 * ks + 1]);

        if (c + 1 < nc) {
            float* Asn = smem + ((c + 1) & 1) * 2 * TILE_F;
            float* Bsn = Asn + TILE_F;
#pragma unroll
            for (int i = 0; i < 4; i++) {
                int row = lrow + (i & 1) * 64;
                int q   = lq + 4 * (i >> 1);
                float* arp = Asn + row * PITCH + q;
                float* brp = Bsn + row * PITCH + q;
                ((uint32_t*)arp)[0]  = f2tf32(sa[i].x);
                ((uint32_t*)arp)[8]  = f2tf32(sa[i].y);
                ((uint32_t*)arp)[16] = f2tf32(sa[i].z);
                ((uint32_t*)arp)[24] = f2tf32(sa[i].w);
                ((uint32_t*)brp)[0]  = f2tf32(sb[i].x);
                ((uint32_t*)brp)[8]  = f2tf32(sb[i].y);
                ((uint32_t*)brp)[16] = f2tf32(sb[i].z);
                ((uint32_t*)brp)[24] = f2tf32(sb[i].w);
            }
            __syncthreads();
        }
    }

#pragma unroll
    for (int mi = 0; mi < 2; mi++) {
        int r0 = m0 + wm * 32 + mi * 16 + (lane >> 2);
#pragma unroll
        for (int ni = 0; ni < 8; ni++) {
            int cc = n0 + wn * 64 + ni * 8 + 2 * (lane & 3);
            float b0 = bias ? bias[cc]     : 0.f;
            float b1 = bias ? bias[cc + 1] : 0.f;
            if (r0 < M) {
                float2 v = make_float2(acc[mi][ni][0] + b0, acc[mi][ni][1] + b1);
                *(float2*)(C + (size_t)r0 * N + cc) = v;
            }
            if (r0 + 8 < M) {
                float2 v = make_float2(acc[mi][ni][2] + b0, acc[mi][ni][3] + b1);
                *(float2*)(C + (size_t)(r0 + 8) * N + cc) = v;
            }
        }
    }
}

// ===========================================================================
// Attention scores + softmax via split-tf32 mma.
// Block = (b, h, 32 q-rows). 8 warps: wm = w&1 (16-row half), wn = w>>1
// (32-col group per 128-key tile).
//   AC: scores[t][s] = (q+posu).k   over 4 key tiles of 128
//   BD: c[t][j] = (q+posv).p[j+511] over 5 j tiles of 128, scatter s=t+j
// smem (uint32): squ hi/lo [64][36], sqv hi/lo [64][36],
//                skp hi/lo [256][36], sc fp32 [32][512]
// ===========================================================================
#define ATTN_SMEM (44032 * 4)   // 176128 bytes

__global__ __launch_bounds__(256, 1)
void attn_mma(const float* __restrict__ posu, const float* __restrict__ posv,
              const int* __restrict__ mask, float* __restrict__ weights)
{
    const int bid   = blockIdx.x;          // 2048 blocks
    const int ttile = bid & 15;
    const int h     = (bid >> 4) & 15;
    const int b     = bid >> 8;
    const int t0    = ttile * 32;

    extern __shared__ __align__(16) uint32_t usm[];
    uint32_t* squ_h = usm;               // [64][36]
    uint32_t* squ_l = usm + 2304;
    uint32_t* sqv_h = usm + 4608;
    uint32_t* sqv_l = usm + 6912;
    uint32_t* skp_h = usm + 9216;        // [256][36]
    uint32_t* skp_l = usm + 18432;
    float*    sc    = (float*)(usm + 27648);   // [32][512]

    const int tid  = threadIdx.x;
    const int lane = tid & 31;
    const int w    = tid >> 5;
    const int wm   = w & 1;
    const int wn   = w >> 1;

    // ---- stage q (+posu / +posv) as hi/lo tf32, kperm layout ----
#pragma unroll
    for (int i = 0; i < 8; i++) {
        int e  = i * 256 + tid;       // 0..2047
        int tt = e >> 6;
        int d  = e & 63;
        float qval = g_qkv[(size_t)(b * T_SEQ + t0 + tt) * THREE_D + h * DK + d];
        int idx = ((d >> 5) * 32 + tt) * 36 + KPERM(d & 31);
        uint32_t hi, lo;
        split_tf32(qval + posu[h * DK + d], hi, lo);
        squ_h[idx] = hi; squ_l[idx] = lo;
        split_tf32(qval + posv[h * DK + d], hi, lo);
        sqv_h[idx] = hi; sqv_l[idx] = lo;
    }
    __syncthreads();

    // hoisted A fragments [chunk][half][j]
    uint32_t ah[2][2][8], al[2][2][8];
#pragma unroll
    for (int c = 0; c < 2; c++) {
        frag_a36(squ_h, c * 32 + wm * 16, lane, ah[c]);
        frag_a36(squ_l, c * 32 + wm * 16, lane, al[c]);
    }

    // ---------------- AC pass ----------------
    for (int st = 0; st < 4; st++) {
        const int s0 = st * 128;
#pragma unroll
        for (int i = 0; i < 32; i++) {
            int e  = i * 256 + tid;
            int ss = e >> 6;
            int d  = e & 63;
            float kv = g_qkv[(size_t)(b * T_SEQ + s0 + ss) * THREE_D + DMODEL + h * DK + d];
            int idx = ((d >> 5) * 128 + ss) * 36 + KPERM(d & 31);
            uint32_t hi, lo;
            split_tf32(kv, hi, lo);
            skp_h[idx] = hi; skp_l[idx] = lo;
        }
        __syncthreads();

        float acc[4][4];
#pragma unroll
        for (int ni = 0; ni < 4; ni++)
#pragma unroll
            for (int r = 0; r < 4; r++) acc[ni][r] = 0.f;

#pragma unroll
        for (int c = 0; c < 2; c++)
#pragma unroll
            for (int ni = 0; ni < 4; ni++) {
                uint32_t bh[8], bl[8];
                frag_b36(skp_h, c * 128 + wn * 32 + ni * 8, lane, bh);
                frag_b36(skp_l, c * 128 + wn * 32 + ni * 8, lane, bl);
#pragma unroll
                for (int ks = 0; ks < 4; ks++)
                    mma3(acc[ni], ah[c], al[c], bh, bl, ks);
            }

        const int rr = wm * 16 + (lane >> 2);
#pragma unroll
        for (int ni = 0; ni < 4; ni++) {
            int col = s0 + wn * 32 + ni * 8 + 2 * (lane & 3);
            *(float2*)&sc[rr * 512 + col]       = make_float2(acc[ni][0], acc[ni][1]);
            *(float2*)&sc[(rr + 8) * 512 + col] = make_float2(acc[ni][2], acc[ni][3]);
        }
        __syncthreads();
    }

    // ---------------- BD pass (diagonal, scatter-add) ----------------
#pragma unroll
    for (int c = 0; c < 2; c++) {
        frag_a36(sqv_h, c * 32 + wm * 16, lane, ah[c]);
        frag_a36(sqv_l, c * 32 + wm * 16, lane, al[c]);
    }

    const int jlo = -(t0 + 31);
    for (int jt = 0; jt < 5; jt++) {
        const int j0 = jlo + jt * 128;
#pragma unroll
        for (int i = 0; i < 32; i++) {
            int e = i * 256 + tid;
            int r = e >> 6;
            int d = e & 63;
            int prow = j0 + r + (T_SEQ - 1);
            float pv = (prow >= 0 && prow < S_REL)
                ? g_p[(size_t)prow * DMODEL + h * DK + d] : 0.f;
            int idx = ((d >> 5) * 128 + r) * 36 + KPERM(d & 31);
            uint32_t hi, lo;
            split_tf32(pv, hi, lo);
            skp_h[idx] = hi; skp_l[idx] = lo;
        }
        __syncthreads();

        float acc[4][4];
#pragma unroll
        for (int ni = 0; ni < 4; ni++)
#pragma unroll
            for (int r = 0; r < 4; r++) acc[ni][r] = 0.f;

#pragma unroll
        for (int c = 0; c < 2; c++)
#pragma unroll
            for (int ni = 0; ni < 4; ni++) {
                uint32_t bh[8], bl[8];
                frag_b36(skp_h, c * 128 + wn * 32 + ni * 8, lane, bh);
                frag_b36(skp_l, c * 128 + wn * 32 + ni * 8, lane, bl);
#pragma unroll
                for (int ks = 0; ks < 4; ks++)
                    mma3(acc[ni], ah[c], al[c], bh, bl, ks);
            }

        const int rr = wm * 16 + (lane >> 2);
#pragma unroll
        for (int ni = 0; ni < 4; ni++) {
            int nl = wn * 32 + ni * 8 + 2 * (lane & 3);
#pragma unroll
            for (int r = 0; r < 4; r++) {
                int trow = rr + (r >> 1) * 8;
                int jg   = j0 + nl + (r & 1);
                int s    = t0 + trow + jg;
                if (s >= 0 && s < T_SEQ)
                    sc[trow * 512 + s] += acc[ni][r];
            }
        }
        __syncthreads();
    }

    // ---------------- scale + mask + softmax + write weights -------------
    const int wid2 = tid >> 5;
    const int lane2 = tid & 31;
#pragma unroll
    for (int rr = 0; rr < 4; rr++) {
        const int tt = wid2 * 4 + rr;
        const int t  = t0 + tt;
        const int* mrow = mask + ((size_t)b * T_SEQ + t) * T_SEQ;

        float mx = -3.4e38f;
        for (int c = lane2; c < T_SEQ; c += 32) {
            float v = sc[tt * 512 + c] * 0.125f;
            v = mrow[c] ? v : -100000.0f;
            sc[tt * 512 + c] = v;
            mx = fmaxf(mx, v);
        }
#pragma unroll
        for (int off = 16; off > 0; off >>= 1)
            mx = fmaxf(mx, __shfl_xor_sync(0xffffffffu, mx, off));

        float sum = 0.f;
        for (int c = lane2; c < T_SEQ; c += 32) {
            float e = __expf(sc[tt * 512 + c] - mx);
            sc[tt * 512 + c] = e;
            sum += e;
        }
#pragma unroll
        for (int off = 16; off > 0; off >>= 1)
            sum += __shfl_xor_sync(0xffffffffu, sum, off);
        float inv = 1.f / sum;

        float* wrow = weights + (((size_t)b * NH + h) * T_SEQ + t) * T_SEQ;
        for (int c = lane2; c < T_SEQ; c += 32)
            wrow[c] = sc[tt * 512 + c] * inv;
    }
}

// ===========================================================================
// ctx = weights @ v via split-tf32 mma.
// Block = (b, h, 64 t-rows); 8 warps: wm = w&3 (16-row group), wn = w>>2
// (32 of the 64 d-cols). k = s in chunks of 64 (2 kperm chunks per iter).
// smem (uint32): ws hi/lo [128][36], vT hi/lo [128][36]
// ===========================================================================
#define CTX_SMEM (18432 * 4)   // 73728 bytes

__global__ __launch_bounds__(256, 2)
void ctx_mma(const float* __restrict__ weights)
{
    const int bid   = blockIdx.x;          // 1024 blocks
    const int ttile = bid & 7;
    const int h     = (bid >> 3) & 15;
    const int b     = bid >> 7;
    const int t0    = ttile * 64;

    extern __shared__ __align__(16) uint32_t usm[];
    uint32_t* ws_h = usm;             // [128][36]
    uint32_t* ws_l = usm + 4608;
    uint32_t* vt_h = usm + 9216;
    uint32_t* vt_l = usm + 13824;

    const int tid  = threadIdx.x;
    const int lane = tid & 31;
    const int w    = tid >> 5;
    const int wm   = w & 3;
    const int wn   = w >> 2;

    float acc[4][4];
#pragma unroll
    for (int ni = 0; ni < 4; ni++)
#pragma unroll
        for (int r = 0; r < 4; r++) acc[ni][r] = 0.f;

    const float* wbase = weights + (((size_t)b * NH + h) * T_SEQ + t0) * T_SEQ;

    for (int s0 = 0; s0 < T_SEQ; s0 += 64) {
        // stage W tile [64 t][64 s] as A (kperm over s)
#pragma unroll
        for (int i = 0; i < 16; i++) {
            int e  = i * 256 + tid;
            int tt = e >> 6;
            int ss = e & 63;
            float v = wbase[(size_t)tt * T_SEQ + s0 + ss];
            int idx = ((ss >> 5) * 64 + tt) * 36 + KPERM(ss & 31);
            uint32_t hi, lo;
            split_tf32(v, hi, lo);
            ws_h[idx] = hi; ws_l[idx] = lo;
        }
        // stage V^T tile: B rows = d, kperm over s
#pragma unroll
        for (int i = 0; i < 16; i++) {
            int e  = i * 256 + tid;
            int sr = e >> 6;
            int d  = e & 63;
            float v = g_qkv[(size_t)(b * T_SEQ + s0 + sr) * THREE_D + 2 * DMODEL + h * DK + d];
            int idx = ((sr >> 5) * 64 + d) * 36 + KPERM(sr & 31);
            uint32_t hi, lo;
            split_tf32(v, hi, lo);
            vt_h[idx] = hi; vt_l[idx] = lo;
        }
        __syncthreads();

#pragma unroll
        for (int c = 0; c < 2; c++) {
            uint32_t ahh[2][8], all_[2][8];
            frag_a36(ws_h, c * 64 + wm * 16, lane, ahh);
            frag_a36(ws_l, c * 64 + wm * 16, lane, all_);
#pragma unroll
            for (int ni = 0; ni < 4; ni++) {
                uint32_t bh[8], bl[8];
                frag_b36(vt_h, c * 64 + wn * 32 + ni * 8, lane, bh);
                frag_b36(vt_l, c * 64 + wn * 32 + ni * 8, lane, bl);
#pragma unroll
                for (int ks = 0; ks < 4; ks++)
                    mma3(acc[ni], ahh, all_, bh, bl, ks);
            }
        }
        __syncthreads();
    }

    const int rr = wm * 16 + (lane >> 2);
#pragma unroll
    for (int ni = 0; ni < 4; ni++) {
        int dcol = wn * 32 + ni * 8 + 2 * (lane & 3);
        float* dst0 = g_ctx + (size_t)(b * T_SEQ + t0 + rr) * DMODEL + h * DK + dcol;
        float* dst1 = g_ctx + (size_t)(b * T_SEQ + t0 + rr + 8) * DMODEL + h * DK + dcol;
        *(float2*)dst0 = make_float2(acc[ni][0], acc[ni][1]);
        *(float2*)dst1 = make_float2(acc[ni][2], acc[ni][3]);
    }
}

// ---------------------------------------------------------------------------
extern "C" void kernel_launch(void* const* d_in, const int* in_sizes, int n_in,
                              void* d_out, int out_size)
{
    const float* x    = (const float*)d_in[0];
    const int*   mask = (const int*)d_in[1];
    const float* pos  = (const float*)d_in[2];
    const float* Wqkv = (const float*)d_in[3];
    const float* bqkv = (const float*)d_in[4];
    const float* Wpos = (const float*)d_in[5];
    const float* posu = (const float*)d_in[6];
    const float* posv = (const float*)d_in[7];
    const float* Wout = (const float*)d_in[8];
    const float* bout = (const float*)d_in[9];

    float* out     = (float*)d_out;
    float* weights = out + (size_t)BT * DMODEL;   // tuple: (out, weights)

    float* qkv_buf; cudaGetSymbolAddress((void**)&qkv_buf, g_qkv);
    float* p_buf;   cudaGetSymbolAddress((void**)&p_buf,   g_p);
    float* ctx_buf; cudaGetSymbolAddress((void**)&ctx_buf, g_ctx);

    cudaFuncSetAttribute(gemm_tf32,
                         cudaFuncAttributeMaxDynamicSharedMemorySize, GEMM_SMEM);
    cudaFuncSetAttribute(attn_mma,
                         cudaFuncAttributeMaxDynamicSharedMemorySize, ATTN_SMEM);
    cudaFuncSetAttribute(ctx_mma,
                         cudaFuncAttributeMaxDynamicSharedMemorySize, CTX_SMEM);

    // 1) QKV projection
    {
        dim3 grid(THREE_D / 128, BT / 128);
        gemm_tf32<<<grid, 256, GEMM_SMEM>>>(x, Wqkv, bqkv, qkv_buf, BT, THREE_D, DMODEL);
    }
    // 2) positional projection
    {
        dim3 grid(DMODEL / 128, (S_REL + 127) / 128);
        gemm_tf32<<<grid, 256, GEMM_SMEM>>>(pos, Wpos, nullptr, p_buf, S_REL, DMODEL, DMODEL);
    }
    // 3) attention scores + softmax -> weights (split-tf32 mma)
    {
        attn_mma<<<BATCH * NH * (T_SEQ / 32), 256, ATTN_SMEM>>>(posu, posv, mask, weights);
    }
    // 4) ctx = weights @ v (split-tf32 mma)
    {
        ctx_mma<<<BATCH * NH * (T_SEQ / 64), 256, CTX_SMEM>>>(weights);
    }
    // 5) out = ctx @ Wout^T + bout
    {
        dim3 grid(DMODEL / 128, BT / 128);
        gemm_tf32<<<grid, 256, GEMM_SMEM>>>(ctx_buf, Wout, bout, out, BT, DMODEL, DMODEL);
    }
}

// round 14
// speedup vs baseline: 1.6126x; 1.6126x over previous
#include <cuda_runtime.h>
#include <cstdint>

// Problem constants
#define BATCH   8
#define T_SEQ   512
#define DMODEL  1024
#define NH      16
#define DK      64
#define S_REL   1023          // 2T-1
#define BT      (BATCH*T_SEQ) // 4096
#define THREE_D (3*DMODEL)    // 3072

// Scratch (device globals; no allocation allowed)
__device__ float g_qkv[BT * THREE_D];   // [B,T, 3D]  (q | k | v per row)
__device__ float g_p[S_REL * DMODEL];   // [S, D] positional projection
__device__ float g_ctx[BT * DMODEL];    // [B,T,D] attention context

// ===========================================================================
// Shared mma helpers
// ===========================================================================
__device__ __forceinline__ uint32_t f2tf32(float f) {
    uint32_t r;
    asm("cvt.rna.tf32.f32 %0, %1;" : "=r"(r) : "f"(f));
    return r;
}
__device__ __forceinline__ void split_tf32(float v, uint32_t& hi, uint32_t& lo) {
    hi = f2tf32(v);
    lo = f2tf32(v - __uint_as_float(hi));
}
__device__ __forceinline__ void mma_tf32(float* d,
                                         uint32_t a0, uint32_t a1, uint32_t a2, uint32_t a3,
                                         uint32_t b0, uint32_t b1) {
    asm volatile(
        "mma.sync.aligned.m16n8k8.row.col.f32.tf32.tf32.f32 "
        "{%0,%1,%2,%3}, {%4,%5,%6,%7}, {%8,%9}, {%0,%1,%2,%3};"
        : "+f"(d[0]), "+f"(d[1]), "+f"(d[2]), "+f"(d[3])
        : "r"(a0), "r"(a1), "r"(a2), "r"(a3), "r"(b0), "r"(b1));
}
// kperm layout: within a 32-wide k chunk, element k stored at (k%4)*8 + k/4.
#define KPERM(k) ((((k)&3)<<3) | ((k)>>2))

// A fragment (m16, all 4 k-steps of a 32-chunk) from a [rows][36] tile
__device__ __forceinline__ void frag_a36(const uint32_t* t, int row0, int lane,
                                         uint32_t a[2][8]) {
#pragma unroll
    for (int hh = 0; hh < 2; hh++) {
        const uint4* p = (const uint4*)(t + (size_t)(row0 + (lane >> 2) + hh * 8) * 36
                                          + (lane & 3) * 8);
        uint4 x = p[0], y = p[1];
        a[hh][0] = x.x; a[hh][1] = x.y; a[hh][2] = x.z; a[hh][3] = x.w;
        a[hh][4] = y.x; a[hh][5] = y.y; a[hh][6] = y.z; a[hh][7] = y.w;
    }
}
// B fragment (n8, all 4 k-steps of a 32-chunk)
__device__ __forceinline__ void frag_b36(const uint32_t* t, int row0, int lane,
                                         uint32_t bfr[8]) {
    const uint4* p = (const uint4*)(t + (size_t)(row0 + (lane >> 2)) * 36
                                      + (lane & 3) * 8);
    uint4 x = p[0], y = p[1];
    bfr[0] = x.x; bfr[1] = x.y; bfr[2] = x.z; bfr[3] = x.w;
    bfr[4] = y.x; bfr[5] = y.y; bfr[6] = y.z; bfr[7] = y.w;
}
// asymmetric split k-step: acc += Ahi*Bhi + Alo*Bhi  (== fp32(A) * tf32(B))
__device__ __forceinline__ void mma2(float* acc,
                                     const uint32_t ah[2][8], const uint32_t al[2][8],
                                     const uint32_t bh[8], int ks) {
    mma_tf32(acc, ah[0][2*ks], ah[1][2*ks], ah[0][2*ks+1], ah[1][2*ks+1],
             bh[2*ks], bh[2*ks+1]);
    mma_tf32(acc, al[0][2*ks], al[1][2*ks], al[0][2*ks+1], al[1][2*ks+1],
             bh[2*ks], bh[2*ks+1]);
}

// ===========================================================================
// tf32 mma.sync GEMM (NT): C[M,N] = A[M,K] @ B[N,K]^T + bias[N]
// (round-8 champion, unchanged)
// ===========================================================================
#define PITCH 36
#define TILE_F (128 * PITCH)
#define GEMM_SMEM (2 * 2 * TILE_F * 4)         // 73728 bytes

__global__ __launch_bounds__(256, 1)
void gemm_tf32(const float* __restrict__ A, const float* __restrict__ Bm,
               const float* __restrict__ bias, float* __restrict__ C,
               int M, int N, int K)
{
    extern __shared__ __align__(16) float smem[];

    const int tid  = threadIdx.x;
    const int lane = tid & 31;
    const int w    = tid >> 5;
    const int wm   = w & 3;
    const int wn   = w >> 2;

    const int n0 = blockIdx.x * 128;
    const int m0 = blockIdx.y * 128;

    const int lrow = w * 8 + (lane >> 2);
    const int lq   = lane & 3;

    float acc[2][8][4];
#pragma unroll
    for (int mi = 0; mi < 2; mi++)
#pragma unroll
        for (int ni = 0; ni < 8; ni++)
#pragma unroll
            for (int r = 0; r < 4; r++) acc[mi][ni][r] = 0.f;

    const int nc = K >> 5;
    float4 sa[4], sb[4];

#pragma unroll
    for (int i = 0; i < 4; i++) {
        int row = lrow + (i & 1) * 64;
        int q   = lq + 4 * (i >> 1);
        sa[i] = make_float4(0.f, 0.f, 0.f, 0.f);
        if (m0 + row < M)
            sa[i] = *(const float4*)(A + (size_t)(m0 + row) * K + q * 4);
        sb[i] = *(const float4*)(Bm + (size_t)(n0 + row) * K + q * 4);
    }
    {
        float* As = smem;
        float* Bs = smem + TILE_F;
#pragma unroll
        for (int i = 0; i < 4; i++) {
            int row = lrow + (i & 1) * 64;
            int q   = lq + 4 * (i >> 1);
            float* ar = As + row * PITCH + q;
            float* br = Bs + row * PITCH + q;
            ((uint32_t*)ar)[0]  = f2tf32(sa[i].x);
            ((uint32_t*)ar)[8]  = f2tf32(sa[i].y);
            ((uint32_t*)ar)[16] = f2tf32(sa[i].z);
            ((uint32_t*)ar)[24] = f2tf32(sa[i].w);
            ((uint32_t*)br)[0]  = f2tf32(sb[i].x);
            ((uint32_t*)br)[8]  = f2tf32(sb[i].y);
            ((uint32_t*)br)[16] = f2tf32(sb[i].z);
            ((uint32_t*)br)[24] = f2tf32(sb[i].w);
        }
    }
    __syncthreads();

    for (int c = 0; c < nc; c++) {
        if (c + 1 < nc) {
            const int k0 = (c + 1) << 5;
#pragma unroll
            for (int i = 0; i < 4; i++) {
                int row = lrow + (i & 1) * 64;
                int q   = lq + 4 * (i >> 1);
                sa[i] = make_float4(0.f, 0.f, 0.f, 0.f);
                if (m0 + row < M)
                    sa[i] = *(const float4*)(A + (size_t)(m0 + row) * K + k0 + q * 4);
                sb[i] = *(const float4*)(Bm + (size_t)(n0 + row) * K + k0 + q * 4);
            }
        }

        const float* As = smem + (c & 1) * 2 * TILE_F;
        const float* Bs = As + TILE_F;

        uint32_t ar[2][2][8];
#pragma unroll
        for (int mi = 0; mi < 2; mi++)
            frag_a36((const uint32_t*)As, wm * 32 + mi * 16, lane, ar[mi]);
        uint32_t br[8][8];
#pragma unroll
        for (int ni = 0; ni < 8; ni++)
            frag_b36((const uint32_t*)Bs, wn * 64 + ni * 8, lane, br[ni]);

#pragma unroll
        for (int ks = 0; ks < 4; ks++)
#pragma unroll
            for (int mi = 0; mi < 2; mi++)
#pragma unroll
                for (int ni = 0; ni < 8; ni++)
                    mma_tf32(acc[mi][ni],
                             ar[mi][0][2 * ks], ar[mi][1][2 * ks],
                             ar[mi][0][2 * ks + 1], ar[mi][1][2 * ks + 1],
                             br[ni][2 * ks], br[ni][2 * ks + 1]);

        if (c + 1 < nc) {
            float* Asn = smem + ((c + 1) & 1) * 2 * TILE_F;
            float* Bsn = Asn + TILE_F;
#pragma unroll
            for (int i = 0; i < 4; i++) {
                int row = lrow + (i & 1) * 64;
                int q   = lq + 4 * (i >> 1);
                float* arp = Asn + row * PITCH + q;
                float* brp = Bsn + row * PITCH + q;
                ((uint32_t*)arp)[0]  = f2tf32(sa[i].x);
                ((uint32_t*)arp)[8]  = f2tf32(sa[i].y);
                ((uint32_t*)arp)[16] = f2tf32(sa[i].z);
                ((uint32_t*)arp)[24] = f2tf32(sa[i].w);
                ((uint32_t*)brp)[0]  = f2tf32(sb[i].x);
                ((uint32_t*)brp)[8]  = f2tf32(sb[i].y);
                ((uint32_t*)brp)[16] = f2tf32(sb[i].z);
                ((uint32_t*)brp)[24] = f2tf32(sb[i].w);
            }
            __syncthreads();
        }
    }

#pragma unroll
    for (int mi = 0; mi < 2; mi++) {
        int r0 = m0 + wm * 32 + mi * 16 + (lane >> 2);
#pragma unroll
        for (int ni = 0; ni < 8; ni++) {
            int cc = n0 + wn * 64 + ni * 8 + 2 * (lane & 3);
            float b0 = bias ? bias[cc]     : 0.f;
            float b1 = bias ? bias[cc + 1] : 0.f;
            if (r0 < M) {
                float2 v = make_float2(acc[mi][ni][0] + b0, acc[mi][ni][1] + b1);
                *(float2*)(C + (size_t)r0 * N + cc) = v;
            }
            if (r0 + 8 < M) {
                float2 v = make_float2(acc[mi][ni][2] + b0, acc[mi][ni][3] + b1);
                *(float2*)(C + (size_t)(r0 + 8) * N + cc) = v;
            }
        }
    }
}

// ===========================================================================
// Attention scores + softmax. A = q (+posu/+posv) split hi/lo (fp32-exact),
// B = K / P plain tf32. Block = (b, h, 32 q-rows); 8 warps (wm=w&1, wn=w>>1).
// smem (u32): squ hi/lo + sqv hi/lo [2][32][36] (9216), skp_h [2][128][36]
// (9216), sc fp32 [32][512] (16384).
// ===========================================================================
#define ATTN_SMEM (34816 * 4)   // 139264 bytes

__global__ __launch_bounds__(256, 1)
void attn_mma(const float* __restrict__ posu, const float* __restrict__ posv,
              const int* __restrict__ mask, float* __restrict__ weights)
{
    const int bid   = blockIdx.x;          // 2048 blocks
    const int ttile = bid & 15;
    const int h     = (bid >> 4) & 15;
    const int b     = bid >> 8;
    const int t0    = ttile * 32;

    extern __shared__ __align__(16) uint32_t usm[];
    uint32_t* squ_h = usm;               // [64][36] (2 chunks x 32 rows)
    uint32_t* squ_l = usm + 2304;
    uint32_t* sqv_h = usm + 4608;
    uint32_t* sqv_l = usm + 6912;
    uint32_t* skp_h = usm + 9216;        // [256][36] (2 chunks x 128 rows)
    float*    sc    = (float*)(usm + 18432);   // [32][512]

    const int tid  = threadIdx.x;
    const int lane = tid & 31;
    const int w    = tid >> 5;
    const int wm   = w & 1;
    const int wn   = w >> 1;

    // ---- stage q (+posu / +posv) hi/lo, kperm layout ----
#pragma unroll
    for (int i = 0; i < 8; i++) {
        int e  = i * 256 + tid;       // 0..2047
        int tt = e >> 6;
        int d  = e & 63;
        float qval = g_qkv[(size_t)(b * T_SEQ + t0 + tt) * THREE_D + h * DK + d];
        int idx = ((d >> 5) * 32 + tt) * 36 + KPERM(d & 31);
        uint32_t hi, lo;
        split_tf32(qval + posu[h * DK + d], hi, lo);
        squ_h[idx] = hi; squ_l[idx] = lo;
        split_tf32(qval + posv[h * DK + d], hi, lo);
        sqv_h[idx] = hi; sqv_l[idx] = lo;
    }
    __syncthreads();

    uint32_t ah[2][2][8], al[2][2][8];
#pragma unroll
    for (int c = 0; c < 2; c++) {
        frag_a36(squ_h, c * 32 + wm * 16, lane, ah[c]);
        frag_a36(squ_l, c * 32 + wm * 16, lane, al[c]);
    }

    // ---------------- AC pass ----------------
    for (int st = 0; st < 4; st++) {
        const int s0 = st * 128;
        // stage K tile (128 x 64) hi only, float4 loads
#pragma unroll
        for (int i = 0; i < 8; i++) {
            int e   = i * 256 + tid;        // float4 index 0..2047
            int row = e >> 4;
            int dq  = (e & 15) * 4;
            float4 kv = *(const float4*)(g_qkv +
                (size_t)(b * T_SEQ + s0 + row) * THREE_D + DMODEL + h * DK + dq);
            uint32_t* base = skp_h + ((dq >> 5) * 128 + row) * 36 + ((dq & 31) >> 2);
            base[0]  = f2tf32(kv.x);
            base[8]  = f2tf32(kv.y);
            base[16] = f2tf32(kv.z);
            base[24] = f2tf32(kv.w);
        }
        __syncthreads();

        float acc[4][4];
#pragma unroll
        for (int ni = 0; ni < 4; ni++)
#pragma unroll
            for (int r = 0; r < 4; r++) acc[ni][r] = 0.f;

#pragma unroll
        for (int c = 0; c < 2; c++)
#pragma unroll
            for (int ni = 0; ni < 4; ni++) {
                uint32_t bh[8];
                frag_b36(skp_h, c * 128 + wn * 32 + ni * 8, lane, bh);
#pragma unroll
                for (int ks = 0; ks < 4; ks++)
                    mma2(acc[ni], ah[c], al[c], bh, ks);
            }

        const int rr = wm * 16 + (lane >> 2);
#pragma unroll
        for (int ni = 0; ni < 4; ni++) {
            int col = s0 + wn * 32 + ni * 8 + 2 * (lane & 3);
            *(float2*)&sc[rr * 512 + col]       = make_float2(acc[ni][0], acc[ni][1]);
            *(float2*)&sc[(rr + 8) * 512 + col] = make_float2(acc[ni][2], acc[ni][3]);
        }
        __syncthreads();
    }

    // ---------------- BD pass (diagonal, scatter-add) ----------------
#pragma unroll
    for (int c = 0; c < 2; c++) {
        frag_a36(sqv_h, c * 32 + wm * 16, lane, ah[c]);
        frag_a36(sqv_l, c * 32 + wm * 16, lane, al[c]);
    }

    const int jlo = -(t0 + 31);
    for (int jt = 0; jt < 5; jt++) {
        const int j0 = jlo + jt * 128;
#pragma unroll
        for (int i = 0; i < 8; i++) {
            int e   = i * 256 + tid;
            int row = e >> 4;
            int dq  = (e & 15) * 4;
            int prow = j0 + row + (T_SEQ - 1);
            float4 pv = make_float4(0.f, 0.f, 0.f, 0.f);
            if (prow >= 0 && prow < S_REL)
                pv = *(const float4*)(g_p + (size_t)prow * DMODEL + h * DK + dq);
            uint32_t* base = skp_h + ((dq >> 5) * 128 + row) * 36 + ((dq & 31) >> 2);
            base[0]  = f2tf32(pv.x);
            base[8]  = f2tf32(pv.y);
            base[16] = f2tf32(pv.z);
            base[24] = f2tf32(pv.w);
        }
        __syncthreads();

        float acc[4][4];
#pragma unroll
        for (int ni = 0; ni < 4; ni++)
#pragma unroll
            for (int r = 0; r < 4; r++) acc[ni][r] = 0.f;

#pragma unroll
        for (int c = 0; c < 2; c++)
#pragma unroll
            for (int ni = 0; ni < 4; ni++) {
                uint32_t bh[8];
                frag_b36(skp_h, c * 128 + wn * 32 + ni * 8, lane, bh);
#pragma unroll
                for (int ks = 0; ks < 4; ks++)
                    mma2(acc[ni], ah[c], al[c], bh, ks);
            }

        const int rr = wm * 16 + (lane >> 2);
#pragma unroll
        for (int ni = 0; ni < 4; ni++) {
            int nl = wn * 32 + ni * 8 + 2 * (lane & 3);
#pragma unroll
            for (int r = 0; r < 4; r++) {
                int trow = rr + (r >> 1) * 8;
                int jg   = j0 + nl + (r & 1);
                int s    = t0 + trow + jg;
                if (s >= 0 && s < T_SEQ)
                    sc[trow * 512 + s] += acc[ni][r];
            }
        }
        __syncthreads();
    }

    // ---------------- scale + mask + softmax + write weights -------------
    const int wid2  = tid >> 5;
    const int lane2 = tid & 31;
#pragma unroll
    for (int rr = 0; rr < 4; rr++) {
        const int tt = wid2 * 4 + rr;
        const int t  = t0 + tt;
        const int* mrow = mask + ((size_t)b * T_SEQ + t) * T_SEQ;

        float mx = -3.4e38f;
        for (int c = lane2; c < T_SEQ; c += 32) {
            float v = sc[tt * 512 + c] * 0.125f;
            v = mrow[c] ? v : -100000.0f;
            sc[tt * 512 + c] = v;
            mx = fmaxf(mx, v);
        }
#pragma unroll
        for (int off = 16; off > 0; off >>= 1)
            mx = fmaxf(mx, __shfl_xor_sync(0xffffffffu, mx, off));

        float sum = 0.f;
        for (int c = lane2; c < T_SEQ; c += 32) {
            float e = __expf(sc[tt * 512 + c] - mx);
            sc[tt * 512 + c] = e;
            sum += e;
        }
#pragma unroll
        for (int off = 16; off > 0; off >>= 1)
            sum += __shfl_xor_sync(0xffffffffu, sum, off);
        float inv = 1.f / sum;

        float* wrow = weights + (((size_t)b * NH + h) * T_SEQ + t) * T_SEQ;
        for (int c = lane2; c < T_SEQ; c += 32)
            wrow[c] = sc[tt * 512 + c] * inv;
    }
}

// ===========================================================================
// ctx = weights @ v. A = weights split hi/lo, B = V^T plain tf32.
// Block = (b, h, 64 t-rows); 8 warps (wm=w&3 row group, wn=w>>2 d half).
// smem (u32): ws hi/lo [128][36] (2x4608), vt_h [128][36] (4608).
// ===========================================================================
#define CTX_SMEM (13824 * 4)   // 55296 bytes

__global__ __launch_bounds__(256, 2)
void ctx_mma(const float* __restrict__ weights)
{
    const int bid   = blockIdx.x;          // 1024 blocks
    const int ttile = bid & 7;
    const int h     = (bid >> 3) & 15;
    const int b     = bid >> 7;
    const int t0    = ttile * 64;

    extern __shared__ __align__(16) uint32_t usm[];
    uint32_t* ws_h = usm;             // [128][36]
    uint32_t* ws_l = usm + 4608;
    uint32_t* vt_h = usm + 9216;      // [128][36]

    const int tid  = threadIdx.x;
    const int lane = tid & 31;
    const int w    = tid >> 5;
    const int wm   = w & 3;
    const int wn   = w >> 2;

    float acc[4][4];
#pragma unroll
    for (int ni = 0; ni < 4; ni++)
#pragma unroll
        for (int r = 0; r < 4; r++) acc[ni][r] = 0.f;

    const float* wbase = weights + (((size_t)b * NH + h) * T_SEQ + t0) * T_SEQ;

    for (int s0 = 0; s0 < T_SEQ; s0 += 64) {
        // stage W tile [64 t][64 s], split hi/lo, float4 loads
#pragma unroll
        for (int i = 0; i < 4; i++) {
            int e  = i * 256 + tid;         // float4 idx 0..1023
            int tt = e >> 4;
            int sq = (e & 15) * 4;
            float4 v = *(const float4*)(wbase + (size_t)tt * T_SEQ + s0 + sq);
            int base = ((sq >> 5) * 64 + tt) * 36 + ((sq & 31) >> 2);
            uint32_t hi, lo;
            split_tf32(v.x, hi, lo); ws_h[base]      = hi; ws_l[base]      = lo;
            split_tf32(v.y, hi, lo); ws_h[base + 8]  = hi; ws_l[base + 8]  = lo;
            split_tf32(v.z, hi, lo); ws_h[base + 16] = hi; ws_l[base + 16] = lo;
            split_tf32(v.w, hi, lo); ws_h[base + 24] = hi; ws_l[base + 24] = lo;
        }
        // stage V^T tile (rows = d, k = s), hi only
#pragma unroll
        for (int i = 0; i < 4; i++) {
            int e  = i * 256 + tid;
            int sr = e >> 4;
            int dd = (e & 15) * 4;
            float4 v = *(const float4*)(g_qkv +
                (size_t)(b * T_SEQ + s0 + sr) * THREE_D + 2 * DMODEL + h * DK + dd);
            uint32_t* base = vt_h + ((sr >> 5) * 64 + dd) * 36
                           + (sr & 3) * 8 + ((sr & 31) >> 2);
            base[0]   = f2tf32(v.x);
            base[36]  = f2tf32(v.y);
            base[72]  = f2tf32(v.z);
            base[108] = f2tf32(v.w);
        }
        __syncthreads();

#pragma unroll
        for (int c = 0; c < 2; c++) {
            uint32_t ahh[2][8], all_[2][8];
            frag_a36(ws_h, c * 64 + wm * 16, lane, ahh);
            frag_a36(ws_l, c * 64 + wm * 16, lane, all_);
#pragma unroll
            for (int ni = 0; ni < 4; ni++) {
                uint32_t bh[8];
                frag_b36(vt_h, c * 64 + wn * 32 + ni * 8, lane, bh);
#pragma unroll
                for (int ks = 0; ks < 4; ks++)
                    mma2(acc[ni], ahh, all_, bh, ks);
            }
        }
        __syncthreads();
    }

    const int rr = wm * 16 + (lane >> 2);
#pragma unroll
    for (int ni = 0; ni < 4; ni++) {
        int dcol = wn * 32 + ni * 8 + 2 * (lane & 3);
        float* dst0 = g_ctx + (size_t)(b * T_SEQ + t0 + rr) * DMODEL + h * DK + dcol;
        float* dst1 = g_ctx + (size_t)(b * T_SEQ + t0 + rr + 8) * DMODEL + h * DK + dcol;
        *(float2*)dst0 = make_float2(acc[ni][0], acc[ni][1]);
        *(float2*)dst1 = make_float2(acc[ni][2], acc[ni][3]);
    }
}

// ---------------------------------------------------------------------------
extern "C" void kernel_launch(void* const* d_in, const int* in_sizes, int n_in,
                              void* d_out, int out_size)
{
    const float* x    = (const float*)d_in[0];
    const int*   mask = (const int*)d_in[1];
    const float* pos  = (const float*)d_in[2];
    const float* Wqkv = (const float*)d_in[3];
    const float* bqkv = (const float*)d_in[4];
    const float* Wpos = (const float*)d_in[5];
    const float* posu = (const float*)d_in[6];
    const float* posv = (const float*)d_in[7];
    const float* Wout = (const float*)d_in[8];
    const float* bout = (const float*)d_in[9];

    float* out     = (float*)d_out;
    float* weights = out + (size_t)BT * DMODEL;   // tuple: (out, weights)

    float* qkv_buf; cudaGetSymbolAddress((void**)&qkv_buf, g_qkv);
    float* p_buf;   cudaGetSymbolAddress((void**)&p_buf,   g_p);
    float* ctx_buf; cudaGetSymbolAddress((void**)&ctx_buf, g_ctx);

    cudaFuncSetAttribute(gemm_tf32,
                         cudaFuncAttributeMaxDynamicSharedMemorySize, GEMM_SMEM);
    cudaFuncSetAttribute(attn_mma,
                         cudaFuncAttributeMaxDynamicSharedMemorySize, ATTN_SMEM);
    cudaFuncSetAttribute(ctx_mma,
                         cudaFuncAttributeMaxDynamicSharedMemorySize, CTX_SMEM);

    // 1) QKV projection
    {
        dim3 grid(THREE_D / 128, BT / 128);
        gemm_tf32<<<grid, 256, GEMM_SMEM>>>(x, Wqkv, bqkv, qkv_buf, BT, THREE_D, DMODEL);
    }
    // 2) positional projection
    {
        dim3 grid(DMODEL / 128, (S_REL + 127) / 128);
        gemm_tf32<<<grid, 256, GEMM_SMEM>>>(pos, Wpos, nullptr, p_buf, S_REL, DMODEL, DMODEL);
    }
    // 3) attention scores + softmax -> weights
    {
        attn_mma<<<BATCH * NH * (T_SEQ / 32), 256, ATTN_SMEM>>>(posu, posv, mask, weights);
    }
    // 4) ctx = weights @ v
    {
        ctx_mma<<<BATCH * NH * (T_SEQ / 64), 256, CTX_SMEM>>>(weights);
    }
    // 5) out = ctx @ Wout^T + bout
    {
        dim3 grid(DMODEL / 128, BT / 128);
        gemm_tf32<<<grid, 256, GEMM_SMEM>>>(ctx_buf, Wout, bout, out, BT, DMODEL, DMODEL);
    }
}